// round 16
// baseline (speedup 1.0000x reference)
#include <cuda_runtime.h>
#include <math.h>
#include <stdint.h>
#include <cuda_bf16.h>

#define NN   8192      // nodes per graph side (B*S)
#define FD   256       // hidden dim
#define FIN0 512       // input dim
#define NE   65536     // directed edges per graph (already symmetric)
#define NB   256       // batch
#define SS   32        // nodes per graph
#define LLY  3         // layers
#define NG   (2 * NB)  // total graphs (q side then c side)
#define XW   (FIN0 / 2)// bf16 pairs per input row (256)
#define FP   (FD / 2)  // bf16 pairs per feature row (128)

// ---- per-block dynamic smem layout (uint32 word offsets) --------------------
// Region 0 time-shared: GEMM staging (Bn+As) -> Ts -> Fpre (phase-disjoint).
#define W_BS    0                        // Bn[2][256][16] = 8192
#define W_AS    8192                     // As[2][64][20]  = 2560
#define REGION0 10752                    // >= Ts 9216, Fpre 8448
#define W_FCUR  REGION0                  // Fcur[64][132] = 8448
#define W_COST  (W_FCUR + 64 * 132)      // cost[3][32*33] = 3168
#define W_DOT   (W_COST + 3 * 32 * 33)   // dot[64]
#define W_SU    (W_DOT + 64)
#define W_R4C   (W_SU + 96)
#define W_C4R   (W_R4C + 96)
#define W_PATH  (W_C4R + 96)
#define W_MC    (W_PATH + 96)
#define W_TOT   (W_MC + 4)               // 22820 words
#define DSM_BYTES (W_TOT * 4)            // 91280 bytes -> 2 blocks/SM

// ---------------- scratch (static device globals; no allocation) -------------
__device__ int      g_adjcnt[NG * SS * SS];
__device__ uint32_t g_adjP[NG * SS * 16];            // normalized adjacency bf16x2
__device__ uint32_t g_xb[2 * NN * XW];               // input x as bf16 pairs
__device__ uint32_t g_wb0[FD * (FIN0 / 2)];          // W n-major, fragment-permuted
__device__ uint32_t g_wb1[FD * (FD / 2)];
__device__ uint32_t g_wb2[FD * (FD / 2)];

// ---------------- helpers ----------------------------------------------------
__device__ __forceinline__ uint32_t pack_bf16x2(float lo, float hi) {
    uint32_t r;
    asm("cvt.rn.bf16x2.f32 %0, %1, %2;" : "=r"(r) : "f"(hi), "f"(lo));
    return r;
}
__device__ __forceinline__ void mma16(float* c, const uint32_t* a,
                                      uint32_t b0, uint32_t b1) {
    asm volatile("mma.sync.aligned.m16n8k16.row.col.f32.bf16.bf16.f32 "
                 "{%0,%1,%2,%3}, {%4,%5,%6,%7}, {%8,%9}, {%0,%1,%2,%3};"
                 : "+f"(c[0]), "+f"(c[1]), "+f"(c[2]), "+f"(c[3])
                 : "r"(a[0]), "r"(a[1]), "r"(a[2]), "r"(a[3]),
                   "r"(b0), "r"(b1));
}
__device__ __forceinline__ void ldsm_x4(uint32_t* r, const uint32_t* p) {
    uint32_t a = (uint32_t)__cvta_generic_to_shared(p);
    asm volatile("ldmatrix.sync.aligned.m8n8.x4.shared.b16 {%0,%1,%2,%3}, [%4];"
                 : "=r"(r[0]), "=r"(r[1]), "=r"(r[2]), "=r"(r[3]) : "r"(a));
}
__device__ __forceinline__ unsigned fkey(float f) {
    unsigned b = __float_as_uint(f);
    return (b & 0x80000000u) ? ~b : (b | 0x80000000u);
}

// ---------------- operand conversion + adjcnt zeroing (once) -----------------
// Weights are stored n-major with fragment-permuted columns:
//   col = stage*16 + la*4 + idx,  idx = kk2g*2 + h,
//   holding W pair kp = stage*16 + kk2g*8 + h*4 + la.
// Then one uint4 at Bn[n][la*4] (per 16-col stage window) yields
// {b0_k0, b1_k0, b0_k1, b1_k1} for a thread with that la.
__global__ void convert_kernel(const float* __restrict__ xq,
                               const float* __restrict__ xc,
                               const float* __restrict__ W0,
                               const float* __restrict__ W1,
                               const float* __restrict__ W2) {
    int t = blockIdx.x * blockDim.x + threadIdx.x;
    const int NXQ = 2 * NN * XW / 4;                 // 1,048,576 x-quads
    if (t < NXQ) {
        int row = t >> 6;
        int q   = t & 63;
        const float* src = (row < NN) ? (xq + (size_t)row * FIN0 + q * 8)
                                      : (xc + (size_t)(row - NN) * FIN0 + q * 8);
        float4 v0 = *(const float4*)src;
        float4 v1 = *(const float4*)(src + 4);
        uint4 o;
        o.x = pack_bf16x2(v0.x, v0.y); o.y = pack_bf16x2(v0.z, v0.w);
        o.z = pack_bf16x2(v1.x, v1.y); o.w = pack_bf16x2(v1.z, v1.w);
        *(uint4*)&g_xb[(size_t)row * XW + q * 4] = o;
        return;
    }
    int u = t - NXQ;
    if (u < 32768) {                                 // weight repack (n-major)
        const float* W; uint32_t* Wo; int nq, KP2;
        if (u < 16384)      { W = W0; Wo = g_wb0; nq = u;         KP2 = 256; }
        else if (u < 24576) { W = W1; Wo = g_wb1; nq = u - 16384; KP2 = 128; }
        else                { W = W2; Wo = g_wb2; nq = u - 24576; KP2 = 128; }
        int col = nq % KP2;
        int n4  = nq / KP2;
        int stage = col >> 4, la = (col >> 2) & 3, idx = col & 3;
        int kp = stage * 16 + (idx >> 1) * 8 + (idx & 1) * 4 + la;
        float4 a = *(const float4*)&W[(size_t)(2 * kp) * FD + n4 * 4];
        float4 b = *(const float4*)&W[(size_t)(2 * kp + 1) * FD + n4 * 4];
        Wo[(size_t)(n4 * 4 + 0) * KP2 + col] = pack_bf16x2(a.x, b.x);
        Wo[(size_t)(n4 * 4 + 1) * KP2 + col] = pack_bf16x2(a.y, b.y);
        Wo[(size_t)(n4 * 4 + 2) * KP2 + col] = pack_bf16x2(a.z, b.z);
        Wo[(size_t)(n4 * 4 + 3) * KP2 + col] = pack_bf16x2(a.w, b.w);
        return;
    }
    int z = u - 32768;                               // zero g_adjcnt
    if (z < NG * SS * SS / 4)
        *(uint4*)&g_adjcnt[z * 4] = make_uint4(0, 0, 0, 0);
}

// ---------------- dense adjacency counts -------------------------------------
__global__ void cnt_kernel(const int* __restrict__ eq,
                           const int* __restrict__ ec) {
    int t = blockIdx.x * blockDim.x + threadIdx.x;   // 2*NE
    int g = (t < NE) ? 0 : 1;
    int e = t - g * NE;
    const int* ei = g ? ec : eq;
    int src = ei[e];
    int dst = ei[NE + e];
    int graph = g * NB + (dst >> 5);
    atomicAdd(&g_adjcnt[graph * (SS * SS) + (dst & 31) * SS + (src & 31)], 1);
}

__global__ void adj_prep_kernel() {       // grid NG, block 32
    int g = blockIdx.x;
    int d = threadIdx.x;
    __shared__ float sdinv[SS];
    const int* cnt = g_adjcnt + g * (SS * SS) + d * SS;
    int deg = 1;                           // self loop
#pragma unroll
    for (int s = 0; s < SS; s++) deg += cnt[s];
    float di = rsqrtf((float)deg);
    sdinv[d] = di;
    __syncwarp();
    uint32_t* outp = g_adjP + g * (SS * 16) + d * 16;
#pragma unroll
    for (int p = 0; p < 16; p++) {
        float a0 = cnt[2 * p]     * di * sdinv[2 * p];
        float a1 = cnt[2 * p + 1] * di * sdinv[2 * p + 1];
        if (d == 2 * p)     a0 += di * di;
        if (d == 2 * p + 1) a1 += di * di;
        outp[p] = pack_bf16x2(a0, a1);
    }
}

// ---------------- MEGA kernel: one batch per block ---------------------------
__global__ void __launch_bounds__(256, 2)
mega_kernel(const float* __restrict__ del_p, const float* __restrict__ ins_p,
            const float* __restrict__ bias0, const float* __restrict__ bias1,
            const float* __restrict__ bias2,
            const float* __restrict__ ot_w, const float* __restrict__ ot_b,
            float* __restrict__ out) {
    extern __shared__ __align__(16) uint32_t dsm[];
    const int bb   = blockIdx.x;          // 0..255 (batch)
    const int tid  = threadIdx.x;
    const int lane = tid & 31;
    const int warp = tid >> 5;            // 0..7
    const int wM = warp >> 2, wN = warp & 3;   // 2x4 warp grid, 32x64 tiles
    const int la = lane & 3, lb = lane >> 2;
    const int lrow = lane & 15;           // ldmatrix row within tile
    const int lcol = (lane >> 4) * 4;     // ldmatrix word-col offset

    uint32_t* Bn   = dsm + W_BS;                         // staged W (n-major frag)
    uint32_t* As   = dsm + W_AS;                         // staged A (layer 0)
    __nv_bfloat16* Ts = (__nv_bfloat16*)dsm;             // [256][72] overlay
    uint32_t* Fpre = dsm;                                // [64][132] overlay
    uint32_t* Fcur = dsm + W_FCUR;                       // [64][132] post-ReLU
    float* costS = (float*)(dsm + W_COST);               // [3][32*33]
    float* dotS  = (float*)(dsm + W_DOT);                // [64]

    // loader mappings
    const int aR = tid >> 2, aW = (tid & 3) * 4;                  // A: 1 uint4
    const int grA = (aR < 32) ? (bb * SS + aR) : (NN + bb * SS + aR - 32);
    const uint32_t* aSrc = g_xb + (size_t)grA * XW + aW;
    int bN[4], bQ[4];                                             // B: 4 uint4
#pragma unroll
    for (int j = 0; j < 4; j++) {
        int s = tid + j * 256;            // uint4 slot 0..1023
        bN[j] = s >> 2;                   // n row 0..255
        bQ[j] = (s & 3) * 4;              // word-quad 0..12
    }

    for (int l = 0; l < LLY; l++) {
        const uint32_t* Wb = (l == 0) ? g_wb0 : ((l == 1) ? g_wb1 : g_wb2);
        const int KP2      = (l == 0) ? 256 : 128;
        const float* bias  = (l == 0) ? bias0 : ((l == 1) ? bias1 : bias2);
        const int nIt = KP2 >> 4;         // 16 / 8 stages

        float acc[2][8][4];
#pragma unroll
        for (int mt = 0; mt < 2; mt++)
#pragma unroll
            for (int nt = 0; nt < 8; nt++)
#pragma unroll
                for (int e = 0; e < 4; e++) acc[mt][nt][e] = 0.f;

        // prefetch stage 0
        uint4 rb[4], ra;
#pragma unroll
        for (int j = 0; j < 4; j++)
            rb[j] = *(const uint4*)(Wb + (size_t)bN[j] * KP2 + bQ[j]);
        if (l == 0) ra = *(const uint4*)(aSrc);

        for (int it = 0; it < nIt; it++) {
            const int buf = it & 1;
#pragma unroll
            for (int j = 0; j < 4; j++)
                *(uint4*)&Bn[buf * 4096 + bN[j] * 16 + bQ[j]] = rb[j];
            if (l == 0)
                *(uint4*)&As[buf * 1280 + aR * 20 + aW] = ra;
            __syncthreads();             // single barrier per stage

            if (it + 1 < nIt) {          // prefetch overlaps compute
                int kw = (it + 1) * 16;
#pragma unroll
                for (int j = 0; j < 4; j++)
                    rb[j] = *(const uint4*)(Wb + (size_t)bN[j] * KP2 + kw + bQ[j]);
                if (l == 0) ra = *(const uint4*)(aSrc + kw);
            }

            // A fragments via ldmatrix (2 k-steps x 2 m-tiles)
            uint32_t aK[2][2][4];
            if (l == 0) {
                const uint32_t* Asb = As + buf * 1280;
#pragma unroll
                for (int ks = 0; ks < 2; ks++)
#pragma unroll
                    for (int mt = 0; mt < 2; mt++)
                        ldsm_x4(aK[ks][mt],
                                Asb + (wM * 32 + mt * 16 + lrow) * 20
                                    + ks * 8 + lcol);
            } else {
#pragma unroll
                for (int ks = 0; ks < 2; ks++)
#pragma unroll
                    for (int mt = 0; mt < 2; mt++)
                        ldsm_x4(aK[ks][mt],
                                Fcur + (wM * 32 + mt * 16 + lrow) * 132
                                     + it * 16 + ks * 8 + lcol);
            }

            const uint32_t* Bnb = Bn + buf * 4096;
#pragma unroll
            for (int nt = 0; nt < 8; nt++) {
                int c = wN * 64 + nt * 8 + lb;
                uint4 bw = *(const uint4*)&Bnb[c * 16 + la * 4];
                mma16(acc[0][nt], aK[0][0], bw.x, bw.y);
                mma16(acc[1][nt], aK[0][1], bw.x, bw.y);
                mma16(acc[0][nt], aK[1][0], bw.z, bw.w);
                mma16(acc[1][nt], aK[1][1], bw.z, bw.w);
            }
        }
        __syncthreads();                 // GEMM reads done; Ts overlays Bn/As

        // ---- stage T transposed to smem (bf16 Ts[col][node], stride 72) ----
#pragma unroll
        for (int mt = 0; mt < 2; mt++)
#pragma unroll
            for (int nt = 0; nt < 8; nt++) {
                int r = wM * 32 + mt * 16 + lb;
                int c = wN * 64 + nt * 8 + la * 2;
                Ts[c * 72 + r]           = __float2bfloat16(acc[mt][nt][0]);
                Ts[(c + 1) * 72 + r]     = __float2bfloat16(acc[mt][nt][1]);
                Ts[c * 72 + r + 8]       = __float2bfloat16(acc[mt][nt][2]);
                Ts[(c + 1) * 72 + r + 8] = __float2bfloat16(acc[mt][nt][3]);
            }
        __syncthreads();

        // ---- aggregation: D = Ahat(graph) @ T + bias ----
        const int gidx = (wM == 0) ? bb : (NB + bb);
        const uint32_t* AhP = g_adjP + gidx * 512;
        uint32_t af[2][2][4];
#pragma unroll
        for (int mt = 0; mt < 2; mt++)
#pragma unroll
            for (int kk = 0; kk < 2; kk++) {
                af[mt][kk][0] = AhP[(mt * 16 + lb) * 16 + kk * 8 + la];
                af[mt][kk][1] = AhP[(mt * 16 + lb + 8) * 16 + kk * 8 + la];
                af[mt][kk][2] = AhP[(mt * 16 + lb) * 16 + kk * 8 + la + 4];
                af[mt][kk][3] = AhP[(mt * 16 + lb + 8) * 16 + kk * 8 + la + 4];
            }
#pragma unroll
        for (int mt = 0; mt < 2; mt++)
#pragma unroll
            for (int nt = 0; nt < 8; nt++) {
                int c = wN * 64 + nt * 8 + la * 2;
                float bx = bias[c], by = bias[c + 1];
                acc[mt][nt][0] = bx; acc[mt][nt][1] = by;
                acc[mt][nt][2] = bx; acc[mt][nt][3] = by;
            }
#pragma unroll
        for (int kk = 0; kk < 2; kk++) {
#pragma unroll
            for (int nt = 0; nt < 8; nt++) {
                int nloc  = wN * 64 + nt * 8 + lb;
                int nodeb = wM * 32 + kk * 16 + 2 * la;
                uint32_t b0 = *(const uint32_t*)&Ts[nloc * 72 + nodeb];
                uint32_t b1 = *(const uint32_t*)&Ts[nloc * 72 + nodeb + 8];
                mma16(acc[0][nt], af[0][kk], b0, b1);
                mma16(acc[1][nt], af[1][kk], b0, b1);
            }
        }
        __syncthreads();                 // Ts reads done; Fpre overlays it

        // ---- write Fpre (pre-ReLU) and Fcur (post-ReLU) ----
#pragma unroll
        for (int mt = 0; mt < 2; mt++)
#pragma unroll
            for (int nt = 0; nt < 8; nt++) {
                int r = wM * 32 + mt * 16 + lb;
                int p = wN * 32 + nt * 4 + la;
                Fpre[r * 132 + p] =
                    pack_bf16x2(acc[mt][nt][0], acc[mt][nt][1]);
                Fpre[(r + 8) * 132 + p] =
                    pack_bf16x2(acc[mt][nt][2], acc[mt][nt][3]);
                if (l < 2) {
                    Fcur[r * 132 + p] =
                        pack_bf16x2(fmaxf(acc[mt][nt][0], 0.f),
                                    fmaxf(acc[mt][nt][1], 0.f));
                    Fcur[(r + 8) * 132 + p] =
                        pack_bf16x2(fmaxf(acc[mt][nt][2], 0.f),
                                    fmaxf(acc[mt][nt][3], 0.f));
                }
            }
        __syncthreads();

        // ---- cost: warps 0-3 mma Q@C^T; warps 4-5 del/ins dots ----
        float ca[2][4];
        const int cwm = (warp >> 1) & 1, cwn = warp & 1;
        if (warp < 4) {
#pragma unroll
            for (int t = 0; t < 2; t++)
#pragma unroll
                for (int e = 0; e < 4; e++) ca[t][e] = 0.f;
            int qr = cwm * 16 + lb;
#pragma unroll 4
            for (int kk = 0; kk < 128; kk += 8) {
                uint32_t a[4];
                a[0] = Fpre[qr * 132 + kk + la];
                a[1] = Fpre[(qr + 8) * 132 + kk + la];
                a[2] = Fpre[qr * 132 + kk + la + 4];
                a[3] = Fpre[(qr + 8) * 132 + kk + la + 4];
#pragma unroll
                for (int t = 0; t < 2; t++) {
                    int cr = 32 + cwn * 16 + t * 8 + lb;
                    uint32_t b0 = Fpre[cr * 132 + kk + la];
                    uint32_t b1 = Fpre[cr * 132 + kk + la + 4];
                    mma16(ca[t], a, b0, b1);
                }
            }
        } else if (warp < 6) {
            int rr = (warp - 4) * 32 + lane;       // 0..63
            const float* vec = (rr < 32) ? (del_p + l * FD) : (ins_p + l * FD);
            float s = 0.f;
#pragma unroll 16
            for (int p2 = 0; p2 < FP; p2++) {
                __nv_bfloat162 h = *(const __nv_bfloat162*)&Fpre[rr * 132 + p2];
                float2 f = __bfloat1622float2(h);
                s += f.x * vec[2 * p2] + f.y * vec[2 * p2 + 1];
            }
            dotS[rr] = s;
        }
        __syncthreads();
        if (warp < 4) {
            float* C = costS + l * (32 * 33);
#pragma unroll
            for (int t = 0; t < 2; t++) {
                int row = cwm * 16 + lb;
                int col = cwn * 16 + t * 8 + 2 * la;
                float dq0 = dotS[row], dq1 = dotS[row + 8];
                float ic0 = dotS[32 + col], ic1 = dotS[32 + col + 1];
                C[row * 33 + col]           = fminf(-ca[t][0], -(dq0 + ic0));
                C[row * 33 + col + 1]       = fminf(-ca[t][1], -(dq0 + ic1));
                C[(row + 8) * 33 + col]     = fminf(-ca[t][2], -(dq1 + ic0));
                C[(row + 8) * 33 + col + 1] = fminf(-ca[t][3], -(dq1 + ic1));
            }
        }
        __syncthreads();
    }

    // ---- 3 LAPs in parallel (warps 0-2), Jonker-Volgenant 32x32 ----
    if (warp < 3) {
        float* C   = costS + warp * (32 * 33);
        float* su  = (float*)(dsm + W_SU)  + warp * 32;
        int* r4c   = (int*)(dsm + W_R4C)   + warp * 32;
        int* c4r   = (int*)(dsm + W_C4R)   + warp * 32;
        int* pth   = (int*)(dsm + W_PATH)  + warp * 32;
        float* mc  = (float*)(dsm + W_MC);

        su[lane] = 0.f;
        r4c[lane] = -1;
        c4r[lane] = -1;
        float v = 0.f;
        __syncwarp();

        const float FINF = __int_as_float(0x7f800000);
        for (int cur = 0; cur < SS; cur++) {
            float sh = FINF;
            bool sc = false;
            int i = cur;
            float minv = 0.f;
            int sink = -1;
            while (sink < 0) {
                float base = minv - su[i];
                if (!sc) {
                    float r = base + C[i * 33 + lane] - v;
                    if (r < sh) { sh = r; pth[lane] = i; }
                }
                unsigned key = sc ? 0xFFFFFFFFu : fkey(sh);
                unsigned mk = __reduce_min_sync(0xffffffffu, key);
                unsigned ball = __ballot_sync(0xffffffffu, key == mk);
                int mj = __ffs(ball) - 1;
                minv = __shfl_sync(0xffffffffu, sh, mj);
                if (lane == mj) sc = true;
                int r4 = r4c[mj];
                if (r4 < 0) sink = mj; else i = r4;
            }
            if (lane == 0) su[cur] += minv;
            if (sc) {
                float d = minv - sh;
                v -= d;
                if (lane != sink) su[r4c[lane]] += d;
            }
            __syncwarp();
            if (lane == 0) {
                int j = sink;
                while (true) {
                    int i2 = pth[j];
                    r4c[j] = i2;
                    int jn = c4r[i2];
                    c4r[i2] = j;
                    j = jn;
                    if (i2 == cur) break;
                }
            }
            __syncwarp();
        }
        float tot = C[r4c[lane] * 33 + lane];
#pragma unroll
        for (int o = 16; o; o >>= 1) tot += __shfl_xor_sync(0xffffffffu, tot, o);
        if (lane == 0) mc[warp] = tot;
    }
    __syncthreads();

    // ---- final score ----
    if (tid == 0) {
        const float* mc = (const float*)(dsm + W_MC);
        float s = ot_b[0];
#pragma unroll
        for (int l = 0; l < LLY; l++)
            s += (mc[l] * (1.0f / 32.0f)) * ot_w[l];
        out[bb] = 1.f / (1.f + expf(-s));
    }
}

// ---------------- launch -----------------------------------------------------
extern "C" void kernel_launch(void* const* d_in, const int* in_sizes, int n_in,
                              void* d_out, int out_size) {
    const float* x_q   = (const float*)d_in[0];
    const float* x_c   = (const float*)d_in[1];
    const float* W0    = (const float*)d_in[2];
    const float* b0    = (const float*)d_in[3];
    const float* W1    = (const float*)d_in[4];
    const float* b1    = (const float*)d_in[5];
    const float* W2    = (const float*)d_in[6];
    const float* b2    = (const float*)d_in[7];
    const float* del_p = (const float*)d_in[8];
    const float* ins_p = (const float*)d_in[9];
    const float* ot_w  = (const float*)d_in[10];
    const float* ot_b  = (const float*)d_in[11];
    const int*   eq    = (const int*)d_in[12];
    const int*   ec    = (const int*)d_in[13];
    float* out = (float*)d_out;

    cudaFuncSetAttribute(mega_kernel,
                         cudaFuncAttributeMaxDynamicSharedMemorySize,
                         DSM_BYTES);

    convert_kernel<<<4736, 256>>>(x_q, x_c, W0, W1, W2);
    cnt_kernel<<<512, 256>>>(eq, ec);
    adj_prep_kernel<<<NG, 32>>>();
    mega_kernel<<<NB, 256, DSM_BYTES>>>(del_p, ins_p, b0, b1, b2,
                                        ot_w, ot_b, out);
}

// round 17
// speedup vs baseline: 1.0351x; 1.0351x over previous
#include <cuda_runtime.h>
#include <math.h>
#include <stdint.h>
#include <cuda_bf16.h>

#define NN   8192      // nodes per graph side (B*S)
#define FD   256       // hidden dim
#define FIN0 512       // input dim
#define NE   65536     // directed edges per graph (already symmetric)
#define NB   256       // batch
#define SS   32        // nodes per graph
#define LLY  3         // layers
#define NG   (2 * NB)  // total graphs (q side then c side)
#define XW   (FIN0 / 2)// bf16 pairs per input row (256)
#define FP   (FD / 2)  // bf16 pairs per feature row (128)

// ---- per-block dynamic smem layout (uint32 word offsets) --------------------
// Region 0 is time-shared: GEMM staging (Bs+As) -> Ts -> Fpre, all phase-disjoint.
#define W_BS    0                        // Bs[2][16][264] = 8448
#define W_AS    (2 * 16 * 264)           // As[2][64][20] = 2560 -> 11008
#define REGION0 (W_AS + 2 * 64 * 20)     // 11008 words (>= Ts 9216, Fpre 8448)
#define W_FCUR  REGION0                  // Fcur[64][132] = 8448
#define W_COST  (W_FCUR + 64 * 132)      // cost[3][32*33] = 3168
#define W_DOT   (W_COST + 3 * 32 * 33)   // dot[64]
#define W_SU    (W_DOT + 64)             // 3*32
#define W_R4C   (W_SU + 96)
#define W_C4R   (W_R4C + 96)
#define W_PATH  (W_C4R + 96)
#define W_MC    (W_PATH + 96)
#define W_TOT   (W_MC + 4)               // 23076 words
#define DSM_BYTES (W_TOT * 4)            // 92304 bytes -> 2 blocks/SM

// ---------------- scratch (static device globals; no allocation) -------------
__device__ int      g_adjcnt[NG * SS * SS];
__device__ uint32_t g_adjP[NG * SS * 16];            // normalized adjacency bf16x2
__device__ uint32_t g_xb[2 * NN * XW];               // input x as bf16 pairs
__device__ uint32_t g_wb0[(FIN0 / 2) * FD];          // W packed (k,k+1) pairs
__device__ uint32_t g_wb1[(FD / 2) * FD];
__device__ uint32_t g_wb2[(FD / 2) * FD];

// ---------------- helpers ----------------------------------------------------
__device__ __forceinline__ uint32_t pack_bf16x2(float lo, float hi) {
    uint32_t r;
    asm("cvt.rn.bf16x2.f32 %0, %1, %2;" : "=r"(r) : "f"(hi), "f"(lo));
    return r;
}
__device__ __forceinline__ void mma16(float* c, const uint32_t* a,
                                      uint32_t b0, uint32_t b1) {
    asm volatile("mma.sync.aligned.m16n8k16.row.col.f32.bf16.bf16.f32 "
                 "{%0,%1,%2,%3}, {%4,%5,%6,%7}, {%8,%9}, {%0,%1,%2,%3};"
                 : "+f"(c[0]), "+f"(c[1]), "+f"(c[2]), "+f"(c[3])
                 : "r"(a[0]), "r"(a[1]), "r"(a[2]), "r"(a[3]),
                   "r"(b0), "r"(b1));
}
__device__ __forceinline__ unsigned fkey(float f) {
    unsigned b = __float_as_uint(f);
    return (b & 0x80000000u) ? ~b : (b | 0x80000000u);
}

// ---------------- operand conversion + adjcnt zeroing (once) -----------------
__global__ void convert_kernel(const float* __restrict__ xq,
                               const float* __restrict__ xc,
                               const float* __restrict__ W0,
                               const float* __restrict__ W1,
                               const float* __restrict__ W2) {
    int t = blockIdx.x * blockDim.x + threadIdx.x;   // quad index
    const int NXQ = 2 * NN * XW / 4;                 // 1,048,576 x-quads
    if (t < NXQ) {
        int row = t >> 6;
        int q   = t & 63;
        const float* src = (row < NN) ? (xq + (size_t)row * FIN0 + q * 8)
                                      : (xc + (size_t)(row - NN) * FIN0 + q * 8);
        float4 v0 = *(const float4*)src;
        float4 v1 = *(const float4*)(src + 4);
        uint4 o;
        o.x = pack_bf16x2(v0.x, v0.y); o.y = pack_bf16x2(v0.z, v0.w);
        o.z = pack_bf16x2(v1.x, v1.y); o.w = pack_bf16x2(v1.z, v1.w);
        *(uint4*)&g_xb[(size_t)row * XW + q * 4] = o;
        return;
    }
    int u = t - NXQ;
    if (u < 32768) {                                 // weight packing
        const float* W; uint32_t* Wo; int nq;
        if (u < 16384)      { W = W0; Wo = g_wb0; nq = u; }
        else if (u < 24576) { W = W1; Wo = g_wb1; nq = u - 16384; }
        else                { W = W2; Wo = g_wb2; nq = u - 24576; }
        int kp = nq >> 6;
        int n4 = (nq & 63) * 4;
        float4 a = *(const float4*)&W[(size_t)(2 * kp) * FD + n4];
        float4 b = *(const float4*)&W[(size_t)(2 * kp + 1) * FD + n4];
        uint4 o;
        o.x = pack_bf16x2(a.x, b.x); o.y = pack_bf16x2(a.y, b.y);
        o.z = pack_bf16x2(a.z, b.z); o.w = pack_bf16x2(a.w, b.w);
        *(uint4*)&Wo[(size_t)kp * FD + n4] = o;
        return;
    }
    int z = u - 32768;                               // zero g_adjcnt
    if (z < NG * SS * SS / 4)
        *(uint4*)&g_adjcnt[z * 4] = make_uint4(0, 0, 0, 0);
}

// ---------------- dense adjacency counts -------------------------------------
__global__ void cnt_kernel(const int* __restrict__ eq,
                           const int* __restrict__ ec) {
    int t = blockIdx.x * blockDim.x + threadIdx.x;   // 2*NE
    int g = (t < NE) ? 0 : 1;
    int e = t - g * NE;
    const int* ei = g ? ec : eq;
    int src = ei[e];
    int dst = ei[NE + e];
    int graph = g * NB + (dst >> 5);
    atomicAdd(&g_adjcnt[graph * (SS * SS) + (dst & 31) * SS + (src & 31)], 1);
}

__global__ void adj_prep_kernel() {       // grid NG, block 32
    int g = blockIdx.x;
    int d = threadIdx.x;
    __shared__ float sdinv[SS];
    const int* cnt = g_adjcnt + g * (SS * SS) + d * SS;
    int deg = 1;                           // self loop
#pragma unroll
    for (int s = 0; s < SS; s++) deg += cnt[s];
    float di = rsqrtf((float)deg);
    sdinv[d] = di;
    __syncwarp();
    uint32_t* outp = g_adjP + g * (SS * 16) + d * 16;
#pragma unroll
    for (int p = 0; p < 16; p++) {
        float a0 = cnt[2 * p]     * di * sdinv[2 * p];
        float a1 = cnt[2 * p + 1] * di * sdinv[2 * p + 1];
        if (d == 2 * p)     a0 += di * di;
        if (d == 2 * p + 1) a1 += di * di;
        outp[p] = pack_bf16x2(a0, a1);
    }
}

// ---------------- MEGA kernel: one batch per block ---------------------------
// Block bb owns q-graph bb (rows 0-31) and c-graph bb (rows 32-63).
// All 3 GCN layers + 3 cost mats + 3 LAPs + score run in shared memory.
__global__ void __launch_bounds__(256, 2)
mega_kernel(const float* __restrict__ del_p, const float* __restrict__ ins_p,
            const float* __restrict__ bias0, const float* __restrict__ bias1,
            const float* __restrict__ bias2,
            const float* __restrict__ ot_w, const float* __restrict__ ot_b,
            float* __restrict__ out) {
    extern __shared__ __align__(16) uint32_t dsm[];
    const int bb   = blockIdx.x;          // 0..255 (batch)
    const int tid  = threadIdx.x;
    const int lane = tid & 31;
    const int warp = tid >> 5;            // 0..7
    const int wM = warp >> 2, wN = warp & 3;   // 2x4 warp grid, 32x64 tiles
    const int la = lane & 3, lb = lane >> 2;

    uint32_t* Bs   = dsm + W_BS;                         // staged W
    uint32_t* As   = dsm + W_AS;                         // staged A (layer 0)
    __nv_bfloat16* Ts = (__nv_bfloat16*)dsm;             // [256][72] overlay
    uint32_t* Fpre = dsm;                                // [64][132] overlay
    uint32_t* Fcur = dsm + W_FCUR;                       // [64][132] post-ReLU
    float* costS = (float*)(dsm + W_COST);               // [3][32*33]
    float* dotS  = (float*)(dsm + W_DOT);                // [64]

    // loader mappings
    const int aR = tid >> 2, aW = (tid & 3) * 4;                  // A: 1 uint4
    const int grA = (aR < 32) ? (bb * SS + aR) : (NN + bb * SS + aR - 32);
    const uint32_t* aSrc = g_xb + (size_t)grA * XW + aW;
    int bkp[4], bw[4];                                            // B: 4 uint4
#pragma unroll
    for (int j = 0; j < 4; j++) {
        bkp[j] = (tid + j * 256) >> 6;
        bw[j]  = ((tid + j * 256) & 63) * 4;
    }

    for (int l = 0; l < LLY; l++) {
        const uint32_t* Wb = (l == 0) ? g_wb0 : ((l == 1) ? g_wb1 : g_wb2);
        const float* bias  = (l == 0) ? bias0 : ((l == 1) ? bias1 : bias2);
        const int nIt = (l == 0) ? 16 : 8;

        float acc[2][8][4];
#pragma unroll
        for (int mt = 0; mt < 2; mt++)
#pragma unroll
            for (int nt = 0; nt < 8; nt++)
#pragma unroll
                for (int e = 0; e < 4; e++) acc[mt][nt][e] = 0.f;

        // prefetch stage 0
        uint4 rb[4], ra;
#pragma unroll
        for (int j = 0; j < 4; j++)
            rb[j] = *(const uint4*)(Wb + (size_t)bkp[j] * FD + bw[j]);
        if (l == 0) ra = *(const uint4*)(aSrc);

        for (int it = 0; it < nIt; it++) {
            const int buf = it & 1;
#pragma unroll
            for (int j = 0; j < 4; j++)
                *(uint4*)&Bs[buf * 4224 + bkp[j] * 264 + bw[j]] = rb[j];
            if (l == 0)
                *(uint4*)&As[buf * 1280 + aR * 20 + aW] = ra;
            __syncthreads();             // single barrier per stage

            if (it + 1 < nIt) {          // prefetch overlaps compute
                int kw = (it + 1) * 16;
#pragma unroll
                for (int j = 0; j < 4; j++)
                    rb[j] = *(const uint4*)(Wb + (size_t)(kw + bkp[j]) * FD + bw[j]);
                if (l == 0) ra = *(const uint4*)(aSrc + kw);
            }

            const uint32_t* Asb = As + buf * 1280;
            const uint32_t* Bsb = Bs + buf * 4224;
#pragma unroll
            for (int kk2 = 0; kk2 < 16; kk2 += 8) {
                uint32_t a[2][4];
#pragma unroll
                for (int mt = 0; mt < 2; mt++) {
                    int r = wM * 32 + mt * 16 + lb;
                    if (l == 0) {
                        a[mt][0] = Asb[r * 20 + kk2 + la];
                        a[mt][1] = Asb[(r + 8) * 20 + kk2 + la];
                        a[mt][2] = Asb[r * 20 + kk2 + la + 4];
                        a[mt][3] = Asb[(r + 8) * 20 + kk2 + la + 4];
                    } else {
                        int kka = it * 16 + kk2 + la;
                        a[mt][0] = Fcur[r * 132 + kka];
                        a[mt][1] = Fcur[(r + 8) * 132 + kka];
                        a[mt][2] = Fcur[r * 132 + kka + 4];
                        a[mt][3] = Fcur[(r + 8) * 132 + kka + 4];
                    }
                }
#pragma unroll
                for (int nt = 0; nt < 8; nt++) {
                    int c = wN * 64 + nt * 8 + lb;
                    uint32_t b0 = Bsb[(kk2 + la) * 264 + c];
                    uint32_t b1 = Bsb[(kk2 + 4 + la) * 264 + c];
                    mma16(acc[0][nt], a[0], b0, b1);
                    mma16(acc[1][nt], a[1], b0, b1);
                }
            }
        }
        __syncthreads();                 // GEMM reads done; Ts overlays Bs/As

        // ---- stage T transposed to smem (bf16 Ts[col][node], stride 72) ----
#pragma unroll
        for (int mt = 0; mt < 2; mt++)
#pragma unroll
            for (int nt = 0; nt < 8; nt++) {
                int r = wM * 32 + mt * 16 + lb;
                int c = wN * 64 + nt * 8 + la * 2;
                Ts[c * 72 + r]           = __float2bfloat16(acc[mt][nt][0]);
                Ts[(c + 1) * 72 + r]     = __float2bfloat16(acc[mt][nt][1]);
                Ts[c * 72 + r + 8]       = __float2bfloat16(acc[mt][nt][2]);
                Ts[(c + 1) * 72 + r + 8] = __float2bfloat16(acc[mt][nt][3]);
            }
        __syncthreads();

        // ---- aggregation: D = Ahat(graph) @ T + bias ----
        const int gidx = (wM == 0) ? bb : (NB + bb);
        const uint32_t* AhP = g_adjP + gidx * 512;
        uint32_t af[2][2][4];
#pragma unroll
        for (int mt = 0; mt < 2; mt++)
#pragma unroll
            for (int kk = 0; kk < 2; kk++) {
                af[mt][kk][0] = AhP[(mt * 16 + lb) * 16 + kk * 8 + la];
                af[mt][kk][1] = AhP[(mt * 16 + lb + 8) * 16 + kk * 8 + la];
                af[mt][kk][2] = AhP[(mt * 16 + lb) * 16 + kk * 8 + la + 4];
                af[mt][kk][3] = AhP[(mt * 16 + lb + 8) * 16 + kk * 8 + la + 4];
            }
#pragma unroll
        for (int mt = 0; mt < 2; mt++)
#pragma unroll
            for (int nt = 0; nt < 8; nt++) {
                int c = wN * 64 + nt * 8 + la * 2;
                float bx = bias[c], by = bias[c + 1];
                acc[mt][nt][0] = bx; acc[mt][nt][1] = by;
                acc[mt][nt][2] = bx; acc[mt][nt][3] = by;
            }
#pragma unroll
        for (int kk = 0; kk < 2; kk++) {
#pragma unroll
            for (int nt = 0; nt < 8; nt++) {
                int nloc  = wN * 64 + nt * 8 + lb;
                int nodeb = wM * 32 + kk * 16 + 2 * la;
                uint32_t b0 = *(const uint32_t*)&Ts[nloc * 72 + nodeb];
                uint32_t b1 = *(const uint32_t*)&Ts[nloc * 72 + nodeb + 8];
                mma16(acc[0][nt], af[0][kk], b0, b1);
                mma16(acc[1][nt], af[1][kk], b0, b1);
            }
        }
        __syncthreads();                 // Ts reads done; Fpre overlays it

        // ---- write Fpre (pre-ReLU) and Fcur (post-ReLU) ----
#pragma unroll
        for (int mt = 0; mt < 2; mt++)
#pragma unroll
            for (int nt = 0; nt < 8; nt++) {
                int r = wM * 32 + mt * 16 + lb;
                int p = wN * 32 + nt * 4 + la;
                Fpre[r * 132 + p] =
                    pack_bf16x2(acc[mt][nt][0], acc[mt][nt][1]);
                Fpre[(r + 8) * 132 + p] =
                    pack_bf16x2(acc[mt][nt][2], acc[mt][nt][3]);
                if (l < 2) {
                    Fcur[r * 132 + p] =
                        pack_bf16x2(fmaxf(acc[mt][nt][0], 0.f),
                                    fmaxf(acc[mt][nt][1], 0.f));
                    Fcur[(r + 8) * 132 + p] =
                        pack_bf16x2(fmaxf(acc[mt][nt][2], 0.f),
                                    fmaxf(acc[mt][nt][3], 0.f));
                }
            }
        __syncthreads();

        // ---- cost: warps 0-3 mma Q@C^T; warps 4-5 del/ins dots ----
        float ca[2][4];
        const int cwm = (warp >> 1) & 1, cwn = warp & 1;
        if (warp < 4) {
#pragma unroll
            for (int t = 0; t < 2; t++)
#pragma unroll
                for (int e = 0; e < 4; e++) ca[t][e] = 0.f;
            int qr = cwm * 16 + lb;
#pragma unroll 4
            for (int kk = 0; kk < 128; kk += 8) {
                uint32_t a[4];
                a[0] = Fpre[qr * 132 + kk + la];
                a[1] = Fpre[(qr + 8) * 132 + kk + la];
                a[2] = Fpre[qr * 132 + kk + la + 4];
                a[3] = Fpre[(qr + 8) * 132 + kk + la + 4];
#pragma unroll
                for (int t = 0; t < 2; t++) {
                    int cr = 32 + cwn * 16 + t * 8 + lb;
                    uint32_t b0 = Fpre[cr * 132 + kk + la];
                    uint32_t b1 = Fpre[cr * 132 + kk + la + 4];
                    mma16(ca[t], a, b0, b1);
                }
            }
        } else if (warp < 6) {
            int rr = (warp - 4) * 32 + lane;       // 0..63
            const float* vec = (rr < 32) ? (del_p + l * FD) : (ins_p + l * FD);
            float s = 0.f;
#pragma unroll 16
            for (int p2 = 0; p2 < FP; p2++) {
                __nv_bfloat162 h = *(const __nv_bfloat162*)&Fpre[rr * 132 + p2];
                float2 f = __bfloat1622float2(h);
                s += f.x * vec[2 * p2] + f.y * vec[2 * p2 + 1];
            }
            dotS[rr] = s;
        }
        __syncthreads();
        if (warp < 4) {
            float* C = costS + l * (32 * 33);
#pragma unroll
            for (int t = 0; t < 2; t++) {
                int row = cwm * 16 + lb;
                int col = cwn * 16 + t * 8 + 2 * la;
                float dq0 = dotS[row], dq1 = dotS[row + 8];
                float ic0 = dotS[32 + col], ic1 = dotS[32 + col + 1];
                C[row * 33 + col]           = fminf(-ca[t][0], -(dq0 + ic0));
                C[row * 33 + col + 1]       = fminf(-ca[t][1], -(dq0 + ic1));
                C[(row + 8) * 33 + col]     = fminf(-ca[t][2], -(dq1 + ic0));
                C[(row + 8) * 33 + col + 1] = fminf(-ca[t][3], -(dq1 + ic1));
            }
        }
        __syncthreads();
    }

    // ---- 3 LAPs in parallel (warps 0-2), Jonker-Volgenant 32x32 ----
    if (warp < 3) {
        float* C   = costS + warp * (32 * 33);
        float* su  = (float*)(dsm + W_SU)  + warp * 32;
        int* r4c   = (int*)(dsm + W_R4C)   + warp * 32;
        int* c4r   = (int*)(dsm + W_C4R)   + warp * 32;
        int* pth   = (int*)(dsm + W_PATH)  + warp * 32;
        float* mc  = (float*)(dsm + W_MC);

        su[lane] = 0.f;
        r4c[lane] = -1;
        c4r[lane] = -1;
        float v = 0.f;
        __syncwarp();

        const float FINF = __int_as_float(0x7f800000);
        for (int cur = 0; cur < SS; cur++) {
            float sh = FINF;
            bool sc = false;
            int i = cur;
            float minv = 0.f;
            int sink = -1;
            while (sink < 0) {
                float base = minv - su[i];
                if (!sc) {
                    float r = base + C[i * 33 + lane] - v;
                    if (r < sh) { sh = r; pth[lane] = i; }
                }
                unsigned key = sc ? 0xFFFFFFFFu : fkey(sh);
                unsigned mk = __reduce_min_sync(0xffffffffu, key);
                unsigned ball = __ballot_sync(0xffffffffu, key == mk);
                int mj = __ffs(ball) - 1;
                minv = __shfl_sync(0xffffffffu, sh, mj);
                if (lane == mj) sc = true;
                int r4 = r4c[mj];
                if (r4 < 0) sink = mj; else i = r4;
            }
            if (lane == 0) su[cur] += minv;
            if (sc) {
                float d = minv - sh;
                v -= d;
                if (lane != sink) su[r4c[lane]] += d;
            }
            __syncwarp();
            if (lane == 0) {
                int j = sink;
                while (true) {
                    int i2 = pth[j];
                    r4c[j] = i2;
                    int jn = c4r[i2];
                    c4r[i2] = j;
                    j = jn;
                    if (i2 == cur) break;
                }
            }
            __syncwarp();
        }
        float tot = C[r4c[lane] * 33 + lane];
#pragma unroll
        for (int o = 16; o; o >>= 1) tot += __shfl_xor_sync(0xffffffffu, tot, o);
        if (lane == 0) mc[warp] = tot;
    }
    __syncthreads();

    // ---- final score ----
    if (tid == 0) {
        const float* mc = (const float*)(dsm + W_MC);
        float s = ot_b[0];
#pragma unroll
        for (int l = 0; l < LLY; l++)
            s += (mc[l] * (1.0f / 32.0f)) * ot_w[l];
        out[bb] = 1.f / (1.f + expf(-s));
    }
}

// ---------------- launch -----------------------------------------------------
extern "C" void kernel_launch(void* const* d_in, const int* in_sizes, int n_in,
                              void* d_out, int out_size) {
    const float* x_q   = (const float*)d_in[0];
    const float* x_c   = (const float*)d_in[1];
    const float* W0    = (const float*)d_in[2];
    const float* b0    = (const float*)d_in[3];
    const float* W1    = (const float*)d_in[4];
    const float* b1    = (const float*)d_in[5];
    const float* W2    = (const float*)d_in[6];
    const float* b2    = (const float*)d_in[7];
    const float* del_p = (const float*)d_in[8];
    const float* ins_p = (const float*)d_in[9];
    const float* ot_w  = (const float*)d_in[10];
    const float* ot_b  = (const float*)d_in[11];
    const int*   eq    = (const int*)d_in[12];
    const int*   ec    = (const int*)d_in[13];
    float* out = (float*)d_out;

    cudaFuncSetAttribute(mega_kernel,
                         cudaFuncAttributeMaxDynamicSharedMemorySize,
                         DSM_BYTES);

    convert_kernel<<<4736, 256>>>(x_q, x_c, W0, W1, W2);
    cnt_kernel<<<512, 256>>>(eq, ec);
    adj_prep_kernel<<<NG, 32>>>();
    mega_kernel<<<NB, 256, DSM_BYTES>>>(del_p, ins_p, b0, b1, b2,
                                        ot_w, ot_b, out);
}